// round 2
// baseline (speedup 1.0000x reference)
#include <cuda_runtime.h>
#include <math.h>

#define BB 16
#define CC 128
#define HH 64
#define WW 64
#define NN 4096      // HH*WW
#define NHH 8
#define HDD 16
#define NHEADS 128   // BB*NHH
#define OUTC 512

// ---------------- scratch (static device globals; no allocation allowed) ----
__device__ float g_s[BB * CC * NN];        //  33.5 MB : CPE output
__device__ float g_qkv[BB * 3 * CC * NN];  // 100.7 MB : q|k|v per batch (b, 384, n)
__device__ float g_lambda[NHEADS * HDD * HDD];
__device__ float g_pool[BB * CC];
__device__ float g_ca[BB * CC];
__device__ float g_r1[BB * CC * NN];       //  33.5 MB : result1

// ============================================================================
// K1: CPE depthwise 3x3 + residual, fused with spatial mean pooling (for ECA)
// one block per (b,c) plane; plane cached in smem
// ============================================================================
__global__ __launch_bounds__(256) void cpe_pool_kernel(
    const float* __restrict__ src, const float* __restrict__ cpe_w)
{
    __shared__ float tile[HH][WW];   // 16 KB
    __shared__ float red[256];

    int bc = blockIdx.x;             // b*128 + c
    int tid = threadIdx.x;
    const float* p = src + (size_t)bc * NN;

    float lsum = 0.f;
    #pragma unroll 4
    for (int i = tid; i < NN; i += 256) {
        float v = p[i];
        tile[i >> 6][i & 63] = v;
        lsum += v;
    }
    red[tid] = lsum;
    __syncthreads();
    for (int s = 128; s > 0; s >>= 1) {
        if (tid < s) red[tid] += red[tid + s];
        __syncthreads();
    }
    if (tid == 0) g_pool[bc] = red[0] * (1.f / (float)NN);

    int c = bc & (CC - 1);
    float w[9];
    #pragma unroll
    for (int j = 0; j < 9; j++) w[j] = cpe_w[c * 9 + j];

    float* sdst = g_s + (size_t)bc * NN;
    for (int i = tid; i < NN; i += 256) {
        int y = i >> 6, x = i & 63;
        float acc = tile[y][x];   // residual
        #pragma unroll
        for (int ky = 0; ky < 3; ky++) {
            int yy = y + ky - 1;
            if ((unsigned)yy >= HH) continue;
            #pragma unroll
            for (int kx = 0; kx < 3; kx++) {
                int xx = x + kx - 1;
                if ((unsigned)xx >= WW) continue;
                acc += w[ky * 3 + kx] * tile[yy][xx];
            }
        }
        sdst[i] = acc;
    }
}

// ============================================================================
// K2: QKV 1x1 conv == GEMM  (384 x 128) @ (128 x 4096) per batch
// BM=128 BN=128 BK=16, 256 threads, 8x8 per thread
// ============================================================================
__global__ __launch_bounds__(256) void qkv_gemm_kernel(const float* __restrict__ qkv_w)
{
    __shared__ float As[16][128];
    __shared__ float Xs[16][128];

    int b  = blockIdx.z;
    int n0 = blockIdx.x * 128;
    int m0 = blockIdx.y * 128;

    const float* X = g_s + (size_t)b * CC * NN;
    float*       Y = g_qkv + (size_t)b * 3 * CC * NN;

    int tid = threadIdx.x;
    int tx = tid & 15, ty = tid >> 4;

    float acc[8][8];
    #pragma unroll
    for (int i = 0; i < 8; i++)
        #pragma unroll
        for (int j = 0; j < 8; j++) acc[i][j] = 0.f;

    for (int k0 = 0; k0 < 128; k0 += 16) {
        #pragma unroll
        for (int r = 0; r < 8; r++) {
            int idx = tid + r * 256;            // 0..2047
            int m  = idx >> 4, kk = idx & 15;
            As[kk][m] = qkv_w[(m0 + m) * 128 + k0 + kk];
            int kk2 = idx >> 7, nn = idx & 127;
            Xs[kk2][nn] = X[(size_t)(k0 + kk2) * NN + n0 + nn];
        }
        __syncthreads();
        #pragma unroll
        for (int kk = 0; kk < 16; kk++) {
            float a[8], xv[8];
            #pragma unroll
            for (int i = 0; i < 8; i++) a[i]  = As[kk][ty * 8 + i];
            #pragma unroll
            for (int j = 0; j < 8; j++) xv[j] = Xs[kk][tx * 8 + j];
            #pragma unroll
            for (int i = 0; i < 8; i++)
                #pragma unroll
                for (int j = 0; j < 8; j++) acc[i][j] += a[i] * xv[j];
        }
        __syncthreads();
    }

    #pragma unroll
    for (int i = 0; i < 8; i++) {
        int m = m0 + ty * 8 + i;
        float* dst = Y + (size_t)m * NN + n0 + tx * 8;
        #pragma unroll
        for (int j = 0; j < 8; j++) dst[j] = acc[i][j];
    }
}

// ============================================================================
// K3: content lambda = softmax(k over N) @ v^T, fused with 1/sqrt(HD) scaling
// one block (512 thr = 16 warps) per head; warp i handles k-row i
// ============================================================================
__global__ __launch_bounds__(512) void lambda_kernel()
{
    int h = blockIdx.x;          // 0..127
    int b = h >> 3, nh = h & 7;
    int warp = threadIdx.x >> 5, lane = threadIdx.x & 31;

    const float* krow  = g_qkv + (size_t)(b * 384 + 128 + nh * 16 + warp) * NN;
    const float* vbase = g_qkv + (size_t)(b * 384 + 256 + nh * 16) * NN;

    float mx = -1e30f;
    #pragma unroll 4
    for (int n = lane; n < NN; n += 32) mx = fmaxf(mx, krow[n]);
    #pragma unroll
    for (int off = 16; off; off >>= 1) mx = fmaxf(mx, __shfl_xor_sync(0xffffffffu, mx, off));

    float sum = 0.f;
    float acc[16];
    #pragma unroll
    for (int o = 0; o < 16; o++) acc[o] = 0.f;

    for (int n = lane; n < NN; n += 32) {
        float p = expf(krow[n] - mx);
        sum += p;
        #pragma unroll
        for (int o = 0; o < 16; o++) acc[o] += p * vbase[(size_t)o * NN + n];
    }
    #pragma unroll
    for (int off = 16; off; off >>= 1) {
        sum += __shfl_xor_sync(0xffffffffu, sum, off);
        #pragma unroll
        for (int o = 0; o < 16; o++) acc[o] += __shfl_xor_sync(0xffffffffu, acc[o], off);
    }
    if (lane == 0) {
        float inv = 0.25f / sum;     // scaling = HD^-0.5 = 0.25 folded in
        #pragma unroll
        for (int o = 0; o < 16; o++)
            g_lambda[(h * 16 + warp) * 16 + o] = acc[o] * inv;
    }
}

// ============================================================================
// K4: result1 = content_output + q * dwconv5x5(v, rel_pos)
// one block per (head, 16x16 spatial tile); v halo in smem
// ============================================================================
__global__ __launch_bounds__(256) void attn_out_kernel(const float* __restrict__ rel_pos)
{
    __shared__ float vs[16][20][20];   // 25.6 KB
    __shared__ float ls[16][16];
    __shared__ float rw[16][25];

    int h = blockIdx.z;
    int b = h >> 3, nh = h & 7;
    int x0 = blockIdx.x * 16, y0 = blockIdx.y * 16;

    const float* vbase = g_qkv + (size_t)(b * 384 + 256 + nh * 16) * NN;
    const float* qbase = g_qkv + (size_t)(b * 384 +   0 + nh * 16) * NN;

    int tid = threadIdx.x;
    int tx = tid & 15, ty = tid >> 4;

    ls[tid >> 4][tid & 15] = g_lambda[h * 256 + tid];
    for (int i = tid; i < 400; i += 256) rw[i / 25][i % 25] = rel_pos[i];

    for (int i = tid; i < 16 * 400; i += 256) {
        int ch = i / 400, r = i % 400;
        int yy = y0 + r / 20 - 2, xx = x0 + (r % 20) - 2;
        float val = 0.f;
        if ((unsigned)yy < HH && (unsigned)xx < WW)
            val = vbase[(size_t)ch * NN + yy * 64 + xx];
        vs[ch][r / 20][r % 20] = val;
    }
    __syncthreads();

    int y = y0 + ty, x = x0 + tx;
    int n = y * 64 + x;

    float q[16];
    #pragma unroll
    for (int i = 0; i < 16; i++) q[i] = qbase[(size_t)i * NN + n];

    float* r1base = g_r1 + (size_t)(b * 128 + nh * 16) * NN + n;
    #pragma unroll
    for (int o = 0; o < 16; o++) {
        float cont = 0.f;
        #pragma unroll
        for (int i = 0; i < 16; i++) cont += q[i] * ls[i][o];
        float pos = 0.f;
        #pragma unroll
        for (int ky = 0; ky < 5; ky++)
            #pragma unroll
            for (int kx = 0; kx < 5; kx++)
                pos += rw[o][ky * 5 + kx] * vs[o][ty + ky][tx + kx];
        r1base[(size_t)o * NN] = cont + q[o] * pos;
    }
}

// ============================================================================
// K5: ECA channel attention from pooled means
// ============================================================================
__global__ __launch_bounds__(128) void ca_kernel(const float* __restrict__ conv1d_w)
{
    int b = blockIdx.x, c = threadIdx.x;
    const float* pp = g_pool + b * CC;
    float pm1 = (c > 0)      ? pp[c - 1] : 0.f;
    float p0  = pp[c];
    float pp1 = (c < CC - 1) ? pp[c + 1] : 0.f;
    float z = conv1d_w[0] * pm1 + conv1d_w[1] * p0 + conv1d_w[2] * pp1;
    g_ca[b * CC + c] = 1.f / (1.f + expf(-z));
}

// ============================================================================
// K6: output projection (512 x 256) @ cat(result1, src*ca)  -- concat + ECA
// scaling fused into the B-operand load. BM=128 BN=128 BK=16, 8x8/thread.
// ============================================================================
__global__ __launch_bounds__(256) void out_gemm_kernel(
    const float* __restrict__ out_w, const float* __restrict__ src,
    float* __restrict__ out)
{
    __shared__ float As[16][128];
    __shared__ float Xs[16][128];

    int b  = blockIdx.z;
    int n0 = blockIdx.x * 128;
    int m0 = blockIdx.y * 128;

    const float* r1b  = g_r1 + (size_t)b * CC * NN;
    const float* srcb = src  + (size_t)b * CC * NN;
    const float* cab  = g_ca + b * CC;

    int tid = threadIdx.x;
    int tx = tid & 15, ty = tid >> 4;

    float acc[8][8];
    #pragma unroll
    for (int i = 0; i < 8; i++)
        #pragma unroll
        for (int j = 0; j < 8; j++) acc[i][j] = 0.f;

    for (int k0 = 0; k0 < 256; k0 += 16) {
        #pragma unroll
        for (int r = 0; r < 8; r++) {
            int idx = tid + r * 256;
            int m = idx >> 4, kk = idx & 15;
            As[kk][m] = out_w[(m0 + m) * 256 + k0 + kk];
            int kk2 = idx >> 7, nn = idx & 127;
            int cgl = k0 + kk2;
            float v;
            if (cgl < 128)
                v = r1b[(size_t)cgl * NN + n0 + nn];
            else
                v = srcb[(size_t)(cgl - 128) * NN + n0 + nn] * cab[cgl - 128];
            Xs[kk2][nn] = v;
        }
        __syncthreads();
        #pragma unroll
        for (int kk = 0; kk < 16; kk++) {
            float a[8], xv[8];
            #pragma unroll
            for (int i = 0; i < 8; i++) a[i]  = As[kk][ty * 8 + i];
            #pragma unroll
            for (int j = 0; j < 8; j++) xv[j] = Xs[kk][tx * 8 + j];
            #pragma unroll
            for (int i = 0; i < 8; i++)
                #pragma unroll
                for (int j = 0; j < 8; j++) acc[i][j] += a[i] * xv[j];
        }
        __syncthreads();
    }

    #pragma unroll
    for (int i = 0; i < 8; i++) {
        int m = m0 + ty * 8 + i;
        float* dst = out + (size_t)(b * OUTC + m) * NN + n0 + tx * 8;
        #pragma unroll
        for (int j = 0; j < 8; j++) dst[j] = acc[i][j];
    }
}

// ============================================================================
extern "C" void kernel_launch(void* const* d_in, const int* in_sizes, int n_in,
                              void* d_out, int out_size)
{
    const float* src      = (const float*)d_in[0];  // (16,128,64,64)
    const float* cpe_w    = (const float*)d_in[1];  // (128,1,3,3)
    const float* qkv_w    = (const float*)d_in[2];  // (384,128)
    const float* rel_pos  = (const float*)d_in[3];  // (16,5,5)
    const float* conv1d_w = (const float*)d_in[4];  // (3,)
    const float* out_w    = (const float*)d_in[5];  // (512,256)
    float* out = (float*)d_out;                     // (16,512,64,64)

    cpe_pool_kernel<<<BB * CC, 256>>>(src, cpe_w);
    ca_kernel<<<BB, 128>>>(conv1d_w);
    qkv_gemm_kernel<<<dim3(NN / 128, 3, BB), 256>>>(qkv_w);
    lambda_kernel<<<NHEADS, 512>>>();
    attn_out_kernel<<<dim3(4, 4, NHEADS), 256>>>(rel_pos);
    out_gemm_kernel<<<dim3(NN / 128, OUTC / 128, BB), 256>>>(out_w, src, out);
}

// round 3
// speedup vs baseline: 1.1615x; 1.1615x over previous
#include <cuda_runtime.h>
#include <math.h>
#include <stdint.h>

#define BB 16
#define CC 128
#define HH 64
#define WW 64
#define NN 4096      // HH*WW
#define NHH 8
#define HDD 16
#define NHEADS 128   // BB*NHH
#define OUTC 512

// ---------------- scratch (static device globals; no allocation allowed) ----
__device__ float g_s[BB * CC * NN];        //  33.5 MB : CPE output
__device__ float g_qkv[BB * 3 * CC * NN];  // 100.7 MB : q|k|v (b, 384, n)
__device__ float g_lambda[NHEADS * HDD * HDD];
__device__ float g_pool[BB * CC];
__device__ float g_ca[BB * CC];
__device__ float g_r1[BB * CC * NN];       //  33.5 MB : result1
__device__ float g_kmax[NHEADS * HDD];     // per (head, k-row) max
__device__ float g_pnum[NHEADS * 8 * 256]; // partial lambda numerators
__device__ float g_pden[NHEADS * 8 * 16];  // partial softmax denominators

// ---------------------------------------------------------------------------
__device__ __forceinline__ float tf32_rna(float x) {
    uint32_t u;
    asm("cvt.rna.tf32.f32 %0, %1;" : "=r"(u) : "f"(x));
    return __uint_as_float(u);
}

__device__ __forceinline__ void mma_tf32(float* d, const float* a, const float* b) {
    asm volatile(
        "mma.sync.aligned.m16n8k8.row.col.f32.tf32.tf32.f32 "
        "{%0,%1,%2,%3}, {%4,%5,%6,%7}, {%8,%9}, {%0,%1,%2,%3};"
        : "+f"(d[0]), "+f"(d[1]), "+f"(d[2]), "+f"(d[3])
        : "r"(__float_as_uint(a[0])), "r"(__float_as_uint(a[1])),
          "r"(__float_as_uint(a[2])), "r"(__float_as_uint(a[3])),
          "r"(__float_as_uint(b[0])), "r"(__float_as_uint(b[1])));
}

// ============================================================================
// K1: CPE depthwise 3x3 + residual, fused with spatial mean pooling (for ECA)
// ============================================================================
__global__ __launch_bounds__(256) void cpe_pool_kernel(
    const float* __restrict__ src, const float* __restrict__ cpe_w)
{
    __shared__ float tile[HH][WW];
    __shared__ float red[256];

    int bc = blockIdx.x;
    int tid = threadIdx.x;
    const float* p = src + (size_t)bc * NN;

    float lsum = 0.f;
    #pragma unroll 4
    for (int i = tid; i < NN; i += 256) {
        float v = p[i];
        tile[i >> 6][i & 63] = v;
        lsum += v;
    }
    red[tid] = lsum;
    __syncthreads();
    for (int s = 128; s > 0; s >>= 1) {
        if (tid < s) red[tid] += red[tid + s];
        __syncthreads();
    }
    if (tid == 0) g_pool[bc] = red[0] * (1.f / (float)NN);

    int c = bc & (CC - 1);
    float w[9];
    #pragma unroll
    for (int j = 0; j < 9; j++) w[j] = cpe_w[c * 9 + j];

    float* sdst = g_s + (size_t)bc * NN;
    for (int i = tid; i < NN; i += 256) {
        int y = i >> 6, x = i & 63;
        float acc = tile[y][x];
        #pragma unroll
        for (int ky = 0; ky < 3; ky++) {
            int yy = y + ky - 1;
            if ((unsigned)yy >= HH) continue;
            #pragma unroll
            for (int kx = 0; kx < 3; kx++) {
                int xx = x + kx - 1;
                if ((unsigned)xx >= WW) continue;
                acc += w[ky * 3 + kx] * tile[yy][xx];
            }
        }
        sdst[i] = acc;
    }
}

// ============================================================================
// K2: QKV GEMM (384 x 128) @ (128 x 4096) per batch, split-tf32 mma.sync
// BM=128 BN=128 BK=16, 8 warps, warp tile 64x32 (4x4 m16n8k8 atoms)
// ============================================================================
__global__ __launch_bounds__(256) void qkv_gemm_kernel(const float* __restrict__ qkv_w)
{
    __shared__ float2 sW[16][136];   // {hi, lo}, [k][m]
    __shared__ float2 sX[16][136];   // {hi, lo}, [k][n]

    int b  = blockIdx.z;
    int n0 = blockIdx.x * 128;
    int m0 = blockIdx.y * 128;

    const float* X = g_s + (size_t)b * CC * NN;
    float*       Y = g_qkv + (size_t)b * 3 * CC * NN;

    int tid  = threadIdx.x;
    int warp = tid >> 5, lane = tid & 31;
    int wm = (warp & 1) * 64;        // warp m offset in tile
    int wn = (warp >> 1) * 32;       // warp n offset
    int ar = lane >> 2, ac = lane & 3;

    float acc[16][4];
    #pragma unroll
    for (int i = 0; i < 16; i++)
        #pragma unroll
        for (int j = 0; j < 4; j++) acc[i][j] = 0.f;

    for (int k0 = 0; k0 < 128; k0 += 16) {
        #pragma unroll
        for (int r = 0; r < 8; r++) {
            int idx = tid + r * 256;          // 0..2047
            int m = idx >> 4, kk = idx & 15;
            float w = qkv_w[(m0 + m) * 128 + k0 + kk];
            float h = tf32_rna(w);
            sW[kk][m] = make_float2(h, tf32_rna(w - h));
            int nn = idx & 127, kk2 = idx >> 7;
            float x = X[(size_t)(k0 + kk2) * NN + n0 + nn];
            float xh = tf32_rna(x);
            sX[kk2][nn] = make_float2(xh, tf32_rna(x - xh));
        }
        __syncthreads();

        #pragma unroll
        for (int ks = 0; ks < 2; ks++) {
            int kb = ks * 8;
            float ah[4][4], al[4][4], bh[4][2], bl[4][2];
            #pragma unroll
            for (int am = 0; am < 4; am++) {
                int mr = wm + am * 16 + ar;
                float2 t0 = sW[kb + ac][mr];
                float2 t1 = sW[kb + ac][mr + 8];
                float2 t2 = sW[kb + ac + 4][mr];
                float2 t3 = sW[kb + ac + 4][mr + 8];
                ah[am][0] = t0.x; al[am][0] = t0.y;
                ah[am][1] = t1.x; al[am][1] = t1.y;
                ah[am][2] = t2.x; al[am][2] = t2.y;
                ah[am][3] = t3.x; al[am][3] = t3.y;
            }
            #pragma unroll
            for (int an = 0; an < 4; an++) {
                int nc = wn + an * 8 + ar;
                float2 u0 = sX[kb + ac][nc];
                float2 u1 = sX[kb + ac + 4][nc];
                bh[an][0] = u0.x; bl[an][0] = u0.y;
                bh[an][1] = u1.x; bl[an][1] = u1.y;
            }
            #pragma unroll
            for (int am = 0; am < 4; am++)
                #pragma unroll
                for (int an = 0; an < 4; an++) {
                    float* d = acc[am * 4 + an];
                    mma_tf32(d, ah[am], bh[an]);
                    mma_tf32(d, al[am], bh[an]);
                    mma_tf32(d, ah[am], bl[an]);
                }
        }
        __syncthreads();
    }

    #pragma unroll
    for (int am = 0; am < 4; am++)
        #pragma unroll
        for (int an = 0; an < 4; an++) {
            const float* d = acc[am * 4 + an];
            int row = m0 + wm + am * 16 + ar;
            int col = n0 + wn + an * 8 + 2 * ac;
            *(float2*)(Y + (size_t)row * NN + col)       = make_float2(d[0], d[1]);
            *(float2*)(Y + (size_t)(row + 8) * NN + col) = make_float2(d[2], d[3]);
        }
}

// ============================================================================
// K3a: per (head, k-row) max over N
// ============================================================================
__global__ __launch_bounds__(256) void kmax_kernel()
{
    int r = blockIdx.x * 8 + (threadIdx.x >> 5);   // 0..2047
    int lane = threadIdx.x & 31;
    int b = r >> 7, rem = r & 127;
    const float* k = g_qkv + (size_t)(b * 384 + 128 + rem) * NN;
    float mx = -1e30f;
    #pragma unroll 4
    for (int n = lane; n < NN; n += 32) mx = fmaxf(mx, k[n]);
    #pragma unroll
    for (int off = 16; off; off >>= 1)
        mx = fmaxf(mx, __shfl_xor_sync(0xffffffffu, mx, off));
    if (lane == 0) g_kmax[r] = mx;
}

// ============================================================================
// K3b: partial lambda over N-chunks: each warp -> 2 k-rows, v shared
// grid (8 chunks, 128 heads), 256 threads
// ============================================================================
__global__ __launch_bounds__(256) void lambda_part_kernel()
{
    int ch = blockIdx.x, h = blockIdx.y;
    int b = h >> 3, nh = h & 7;
    int warp = threadIdx.x >> 5, lane = threadIdx.x & 31;
    int i0 = warp * 2;

    const float* kbase = g_qkv + (size_t)(b * 384 + 128 + nh * 16) * NN;
    const float* vbase = g_qkv + (size_t)(b * 384 + 256 + nh * 16) * NN;
    const float* k0p = kbase + (size_t)i0 * NN;
    const float* k1p = k0p + NN;
    float mx0 = g_kmax[h * 16 + i0];
    float mx1 = g_kmax[h * 16 + i0 + 1];

    float acc0[16], acc1[16], s0 = 0.f, s1 = 0.f;
    #pragma unroll
    for (int o = 0; o < 16; o++) { acc0[o] = 0.f; acc1[o] = 0.f; }

    int nbeg = ch * 512 + lane;
    #pragma unroll 2
    for (int it = 0; it < 16; it++) {
        int n = nbeg + it * 32;
        float p0 = __expf(k0p[n] - mx0);
        float p1 = __expf(k1p[n] - mx1);
        s0 += p0; s1 += p1;
        #pragma unroll
        for (int o = 0; o < 16; o++) {
            float vv = vbase[(size_t)o * NN + n];
            acc0[o] += p0 * vv;
            acc1[o] += p1 * vv;
        }
    }
    #pragma unroll
    for (int off = 16; off; off >>= 1) {
        s0 += __shfl_xor_sync(0xffffffffu, s0, off);
        s1 += __shfl_xor_sync(0xffffffffu, s1, off);
        #pragma unroll
        for (int o = 0; o < 16; o++) {
            acc0[o] += __shfl_xor_sync(0xffffffffu, acc0[o], off);
            acc1[o] += __shfl_xor_sync(0xffffffffu, acc1[o], off);
        }
    }
    if (lane == 0) {
        float* pn = g_pnum + (size_t)(h * 8 + ch) * 256;
        #pragma unroll
        for (int o = 0; o < 16; o++) {
            pn[i0 * 16 + o]       = acc0[o];
            pn[(i0 + 1) * 16 + o] = acc1[o];
        }
        g_pden[(h * 8 + ch) * 16 + i0]     = s0;
        g_pden[(h * 8 + ch) * 16 + i0 + 1] = s1;
    }
}

// ============================================================================
// K3c: combine partials -> lambda (with 0.25 scaling folded in)
// ============================================================================
__global__ __launch_bounds__(256) void lambda_comb_kernel()
{
    int h = blockIdx.x, t = threadIdx.x;
    int i = t >> 4;
    float num = 0.f, den = 0.f;
    #pragma unroll
    for (int ch = 0; ch < 8; ch++) {
        num += g_pnum[(size_t)(h * 8 + ch) * 256 + t];
        den += g_pden[(h * 8 + ch) * 16 + i];
    }
    g_lambda[h * 256 + t] = 0.25f * num / den;
}

// ============================================================================
// K4: result1 = content_output + q * dwconv5x5(v, rel_pos)
// ============================================================================
__global__ __launch_bounds__(256) void attn_out_kernel(const float* __restrict__ rel_pos)
{
    __shared__ float vs[16][20][20];
    __shared__ float ls[16][16];
    __shared__ float rw[16][25];

    int h = blockIdx.z;
    int b = h >> 3, nh = h & 7;
    int x0 = blockIdx.x * 16, y0 = blockIdx.y * 16;

    const float* vbase = g_qkv + (size_t)(b * 384 + 256 + nh * 16) * NN;
    const float* qbase = g_qkv + (size_t)(b * 384 +   0 + nh * 16) * NN;

    int tid = threadIdx.x;
    int tx = tid & 15, ty = tid >> 4;

    ls[tid >> 4][tid & 15] = g_lambda[h * 256 + tid];
    for (int i = tid; i < 400; i += 256) rw[i / 25][i % 25] = rel_pos[i];

    for (int i = tid; i < 16 * 400; i += 256) {
        int chn = i / 400, r = i % 400;
        int yy = y0 + r / 20 - 2, xx = x0 + (r % 20) - 2;
        float val = 0.f;
        if ((unsigned)yy < HH && (unsigned)xx < WW)
            val = vbase[(size_t)chn * NN + yy * 64 + xx];
        vs[chn][r / 20][r % 20] = val;
    }
    __syncthreads();

    int y = y0 + ty, x = x0 + tx;
    int n = y * 64 + x;

    float q[16];
    #pragma unroll
    for (int i = 0; i < 16; i++) q[i] = qbase[(size_t)i * NN + n];

    float* r1base = g_r1 + (size_t)(b * 128 + nh * 16) * NN + n;
    #pragma unroll
    for (int o = 0; o < 16; o++) {
        float cont = 0.f;
        #pragma unroll
        for (int i = 0; i < 16; i++) cont += q[i] * ls[i][o];
        float pos = 0.f;
        #pragma unroll
        for (int ky = 0; ky < 5; ky++)
            #pragma unroll
            for (int kx = 0; kx < 5; kx++)
                pos += rw[o][ky * 5 + kx] * vs[o][ty + ky][tx + kx];
        r1base[(size_t)o * NN] = cont + q[o] * pos;
    }
}

// ============================================================================
// K5: ECA channel attention from pooled means
// ============================================================================
__global__ __launch_bounds__(128) void ca_kernel(const float* __restrict__ conv1d_w)
{
    int b = blockIdx.x, c = threadIdx.x;
    const float* pp = g_pool + b * CC;
    float pm1 = (c > 0)      ? pp[c - 1] : 0.f;
    float p0  = pp[c];
    float pp1 = (c < CC - 1) ? pp[c + 1] : 0.f;
    float z = conv1d_w[0] * pm1 + conv1d_w[1] * p0 + conv1d_w[2] * pp1;
    g_ca[b * CC + c] = 1.f / (1.f + expf(-z));
}

// ============================================================================
// K6: output projection (512 x 256) @ cat(result1, src*ca), split-tf32 mma
// ============================================================================
__global__ __launch_bounds__(256) void out_gemm_kernel(
    const float* __restrict__ out_w, const float* __restrict__ src,
    float* __restrict__ out)
{
    __shared__ float2 sW[16][136];
    __shared__ float2 sX[16][136];

    int b  = blockIdx.z;
    int n0 = blockIdx.x * 128;
    int m0 = blockIdx.y * 128;

    const float* r1b  = g_r1 + (size_t)b * CC * NN;
    const float* srcb = src  + (size_t)b * CC * NN;
    const float* cab  = g_ca + b * CC;

    int tid  = threadIdx.x;
    int warp = tid >> 5, lane = tid & 31;
    int wm = (warp & 1) * 64;
    int wn = (warp >> 1) * 32;
    int ar = lane >> 2, ac = lane & 3;

    float acc[16][4];
    #pragma unroll
    for (int i = 0; i < 16; i++)
        #pragma unroll
        for (int j = 0; j < 4; j++) acc[i][j] = 0.f;

    for (int k0 = 0; k0 < 256; k0 += 16) {
        #pragma unroll
        for (int r = 0; r < 8; r++) {
            int idx = tid + r * 256;
            int m = idx >> 4, kk = idx & 15;
            float w = out_w[(m0 + m) * 256 + k0 + kk];
            float h = tf32_rna(w);
            sW[kk][m] = make_float2(h, tf32_rna(w - h));
            int nn = idx & 127, kk2 = idx >> 7;
            int cgl = k0 + kk2;
            float x;
            if (cgl < 128)
                x = r1b[(size_t)cgl * NN + n0 + nn];
            else
                x = srcb[(size_t)(cgl - 128) * NN + n0 + nn] * cab[cgl - 128];
            float xh = tf32_rna(x);
            sX[kk2][nn] = make_float2(xh, tf32_rna(x - xh));
        }
        __syncthreads();

        #pragma unroll
        for (int ks = 0; ks < 2; ks++) {
            int kb = ks * 8;
            float ah[4][4], al[4][4], bh[4][2], bl[4][2];
            #pragma unroll
            for (int am = 0; am < 4; am++) {
                int mr = wm + am * 16 + ar;
                float2 t0 = sW[kb + ac][mr];
                float2 t1 = sW[kb + ac][mr + 8];
                float2 t2 = sW[kb + ac + 4][mr];
                float2 t3 = sW[kb + ac + 4][mr + 8];
                ah[am][0] = t0.x; al[am][0] = t0.y;
                ah[am][1] = t1.x; al[am][1] = t1.y;
                ah[am][2] = t2.x; al[am][2] = t2.y;
                ah[am][3] = t3.x; al[am][3] = t3.y;
            }
            #pragma unroll
            for (int an = 0; an < 4; an++) {
                int nc = wn + an * 8 + ar;
                float2 u0 = sX[kb + ac][nc];
                float2 u1 = sX[kb + ac + 4][nc];
                bh[an][0] = u0.x; bl[an][0] = u0.y;
                bh[an][1] = u1.x; bl[an][1] = u1.y;
            }
            #pragma unroll
            for (int am = 0; am < 4; am++)
                #pragma unroll
                for (int an = 0; an < 4; an++) {
                    float* d = acc[am * 4 + an];
                    mma_tf32(d, ah[am], bh[an]);
                    mma_tf32(d, al[am], bh[an]);
                    mma_tf32(d, ah[am], bl[an]);
                }
        }
        __syncthreads();
    }

    #pragma unroll
    for (int am = 0; am < 4; am++)
        #pragma unroll
        for (int an = 0; an < 4; an++) {
            const float* d = acc[am * 4 + an];
            int row = m0 + wm + am * 16 + ar;
            int col = n0 + wn + an * 8 + 2 * ac;
            float* dst = out + (size_t)(b * OUTC + row) * NN + col;
            *(float2*)dst              = make_float2(d[0], d[1]);
            *(float2*)(dst + 8 * NN)   = make_float2(d[2], d[3]);
        }
}

// ============================================================================
extern "C" void kernel_launch(void* const* d_in, const int* in_sizes, int n_in,
                              void* d_out, int out_size)
{
    const float* src      = (const float*)d_in[0];  // (16,128,64,64)
    const float* cpe_w    = (const float*)d_in[1];  // (128,1,3,3)
    const float* qkv_w    = (const float*)d_in[2];  // (384,128)
    const float* rel_pos  = (const float*)d_in[3];  // (16,5,5)
    const float* conv1d_w = (const float*)d_in[4];  // (3,)
    const float* out_w    = (const float*)d_in[5];  // (512,256)
    float* out = (float*)d_out;                     // (16,512,64,64)

    cpe_pool_kernel<<<BB * CC, 256>>>(src, cpe_w);
    ca_kernel<<<BB, 128>>>(conv1d_w);
    qkv_gemm_kernel<<<dim3(NN / 128, 3, BB), 256>>>(qkv_w);
    kmax_kernel<<<NHEADS * HDD / 8, 256>>>();
    lambda_part_kernel<<<dim3(8, NHEADS), 256>>>();
    lambda_comb_kernel<<<NHEADS, 256>>>();
    attn_out_kernel<<<dim3(4, 4, NHEADS), 256>>>(rel_pos);
    out_gemm_kernel<<<dim3(NN / 128, OUTC / 128, BB), 256>>>(out_w, src, out);
}

// round 7
// speedup vs baseline: 2.2962x; 1.9770x over previous
#include <cuda_runtime.h>
#include <cuda_bf16.h>
#include <math.h>
#include <stdint.h>

#define BB 16
#define CC 128
#define HH 64
#define WW 64
#define NN 4096      // HH*WW
#define NHH 8
#define HDD 16
#define NHEADS 128   // BB*NHH
#define OUTC 512

// ---------------- scratch (static device globals; no allocation allowed) ----
__device__ float g_s[BB * CC * NN];        //  33.5 MB : CPE output
__device__ float g_qkv[BB * 3 * CC * NN];  // 100.7 MB : q|k|v (b, 384, n)
__device__ float g_lambda[NHEADS * HDD * HDD];
__device__ float g_pool[BB * CC];
__device__ float g_ca[BB * CC];
__device__ float g_r1[BB * CC * NN];       //  33.5 MB : result1
__device__ float g_kmax[NHEADS * HDD];
__device__ float g_pnum[NHEADS * 8 * 256];
__device__ float g_pden[NHEADS * 8 * 16];

// ---------------------------------------------------------------------------
// split fp32 -> hi/lo bf16, packed two consecutive-k values per 32-bit word
__device__ __forceinline__ void bf16_split2(float x0, float x1,
                                            uint32_t& hi, uint32_t& lo)
{
    __nv_bfloat16 h0 = __float2bfloat16_rn(x0);
    __nv_bfloat16 h1 = __float2bfloat16_rn(x1);
    __nv_bfloat16 l0 = __float2bfloat16_rn(x0 - __bfloat162float(h0));
    __nv_bfloat16 l1 = __float2bfloat16_rn(x1 - __bfloat162float(h1));
    hi = ((uint32_t)__bfloat16_as_ushort(h1) << 16) | __bfloat16_as_ushort(h0);
    lo = ((uint32_t)__bfloat16_as_ushort(l1) << 16) | __bfloat16_as_ushort(l0);
}

__device__ __forceinline__ void mma_bf16(float* d, const uint32_t* a, const uint32_t* b)
{
    asm volatile(
        "mma.sync.aligned.m16n8k16.row.col.f32.bf16.bf16.f32 "
        "{%0,%1,%2,%3}, {%4,%5,%6,%7}, {%8,%9}, {%0,%1,%2,%3};"
        : "+f"(d[0]), "+f"(d[1]), "+f"(d[2]), "+f"(d[3])
        : "r"(a[0]), "r"(a[1]), "r"(a[2]), "r"(a[3]), "r"(b[0]), "r"(b[1]));
}

// ============================================================================
// K1: CPE depthwise 3x3 + residual, fused with spatial mean pooling (for ECA)
// ============================================================================
__global__ __launch_bounds__(256) void cpe_pool_kernel(
    const float* __restrict__ src, const float* __restrict__ cpe_w)
{
    __shared__ float tile[HH][WW];
    __shared__ float red[256];

    int bc = blockIdx.x;
    int tid = threadIdx.x;
    const float* p = src + (size_t)bc * NN;

    float lsum = 0.f;
    #pragma unroll 4
    for (int i = tid; i < NN; i += 256) {
        float v = p[i];
        tile[i >> 6][i & 63] = v;
        lsum += v;
    }
    red[tid] = lsum;
    __syncthreads();
    for (int s = 128; s > 0; s >>= 1) {
        if (tid < s) red[tid] += red[tid + s];
        __syncthreads();
    }
    if (tid == 0) g_pool[bc] = red[0] * (1.f / (float)NN);

    int c = bc & (CC - 1);
    float w[9];
    #pragma unroll
    for (int j = 0; j < 9; j++) w[j] = cpe_w[c * 9 + j];

    float* sdst = g_s + (size_t)bc * NN;
    for (int i = tid; i < NN; i += 256) {
        int y = i >> 6, x = i & 63;
        float acc = tile[y][x];
        #pragma unroll
        for (int ky = 0; ky < 3; ky++) {
            int yy = y + ky - 1;
            if ((unsigned)yy >= HH) continue;
            #pragma unroll
            for (int kx = 0; kx < 3; kx++) {
                int xx = x + kx - 1;
                if ((unsigned)xx >= WW) continue;
                acc += w[ky * 3 + kx] * tile[yy][xx];
            }
        }
        sdst[i] = acc;
    }
}

// ============================================================================
// K2: QKV GEMM (384 x 128) @ (128 x 4096) per batch, split-bf16 m16n8k16 mma
// BM=128 BN=128 BK=16, 8 warps, warp tile 64x32 (4x4 atoms)
// ============================================================================
__global__ __launch_bounds__(256) void qkv_gemm_kernel(const float* __restrict__ qkv_w)
{
    __shared__ uint32_t sWh[8][132], sWl[8][132];  // [k8][m], bf16x2 along k
    __shared__ uint32_t sXh[8][132], sXl[8][132];  // [k8][n]

    int b  = blockIdx.z;
    int n0 = blockIdx.x * 128;
    int m0 = blockIdx.y * 128;

    const float* X = g_s + (size_t)b * CC * NN;
    float*       Y = g_qkv + (size_t)b * 3 * CC * NN;

    int tid  = threadIdx.x;
    int warp = tid >> 5, lane = tid & 31;
    int wm = (warp & 1) * 64;        // warp m offset
    int wn = (warp >> 1) * 32;       // warp n offset
    int gid = lane >> 2, tig = lane & 3;

    float acc[16][4];
    #pragma unroll
    for (int i = 0; i < 16; i++)
        #pragma unroll
        for (int j = 0; j < 4; j++) acc[i][j] = 0.f;

    for (int k0 = 0; k0 < 128; k0 += 16) {
        // A: W[m0..+128][k0..+16] -> pairs along k
        #pragma unroll
        for (int r = 0; r < 4; r++) {
            int idx = tid + r * 256;         // 0..1023
            int m = idx >> 3, k8 = idx & 7;
            float2 w2 = *(const float2*)&qkv_w[(m0 + m) * 128 + k0 + k8 * 2];
            bf16_split2(w2.x, w2.y, sWh[k8][m], sWl[k8][m]);
            // B: X[k0..+16][n0..+128] -> pairs along k
            int n = idx & 127, k8b = idx >> 7;
            float x0 = X[(size_t)(k0 + k8b * 2)     * NN + n0 + n];
            float x1 = X[(size_t)(k0 + k8b * 2 + 1) * NN + n0 + n];
            bf16_split2(x0, x1, sXh[k8b][n], sXl[k8b][n]);
        }
        __syncthreads();

        uint32_t ah[4][4], al[4][4], bh[4][2], bl[4][2];
        #pragma unroll
        for (int am = 0; am < 4; am++) {
            int mr = wm + am * 16 + gid;
            ah[am][0] = sWh[tig][mr];     al[am][0] = sWl[tig][mr];
            ah[am][1] = sWh[tig][mr + 8]; al[am][1] = sWl[tig][mr + 8];
            ah[am][2] = sWh[tig + 4][mr];     al[am][2] = sWl[tig + 4][mr];
            ah[am][3] = sWh[tig + 4][mr + 8]; al[am][3] = sWl[tig + 4][mr + 8];
        }
        #pragma unroll
        for (int an = 0; an < 4; an++) {
            int nc = wn + an * 8 + gid;
            bh[an][0] = sXh[tig][nc];     bl[an][0] = sXl[tig][nc];
            bh[an][1] = sXh[tig + 4][nc]; bl[an][1] = sXl[tig + 4][nc];
        }
        #pragma unroll
        for (int am = 0; am < 4; am++)
            #pragma unroll
            for (int an = 0; an < 4; an++) {
                float* d = acc[am * 4 + an];
                mma_bf16(d, ah[am], bh[an]);
                mma_bf16(d, al[am], bh[an]);
                mma_bf16(d, ah[am], bl[an]);
            }
        __syncthreads();
    }

    #pragma unroll
    for (int am = 0; am < 4; am++)
        #pragma unroll
        for (int an = 0; an < 4; an++) {
            const float* d = acc[am * 4 + an];
            int row = m0 + wm + am * 16 + gid;
            int col = n0 + wn + an * 8 + 2 * tig;
            *(float2*)(Y + (size_t)row * NN + col)       = make_float2(d[0], d[1]);
            *(float2*)(Y + (size_t)(row + 8) * NN + col) = make_float2(d[2], d[3]);
        }
}

// ============================================================================
// K3a: per (head, k-row) max over N
// ============================================================================
__global__ __launch_bounds__(256) void kmax_kernel()
{
    int r = blockIdx.x * 8 + (threadIdx.x >> 5);
    int lane = threadIdx.x & 31;
    int b = r >> 7, rem = r & 127;
    const float* k = g_qkv + (size_t)(b * 384 + 128 + rem) * NN;
    float mx = -1e30f;
    #pragma unroll 4
    for (int n = lane; n < NN; n += 32) mx = fmaxf(mx, k[n]);
    #pragma unroll
    for (int off = 16; off; off >>= 1)
        mx = fmaxf(mx, __shfl_xor_sync(0xffffffffu, mx, off));
    if (lane == 0) g_kmax[r] = mx;
}

// ============================================================================
// K3b: partial lambda over N-chunks: each warp -> 2 k-rows, v shared
// ============================================================================
__global__ __launch_bounds__(256) void lambda_part_kernel()
{
    int ch = blockIdx.x, h = blockIdx.y;
    int b = h >> 3, nh = h & 7;
    int warp = threadIdx.x >> 5, lane = threadIdx.x & 31;
    int i0 = warp * 2;

    const float* kbase = g_qkv + (size_t)(b * 384 + 128 + nh * 16) * NN;
    const float* vbase = g_qkv + (size_t)(b * 384 + 256 + nh * 16) * NN;
    const float* k0p = kbase + (size_t)i0 * NN;
    const float* k1p = k0p + NN;
    float mx0 = g_kmax[h * 16 + i0];
    float mx1 = g_kmax[h * 16 + i0 + 1];

    float acc0[16], acc1[16], s0 = 0.f, s1 = 0.f;
    #pragma unroll
    for (int o = 0; o < 16; o++) { acc0[o] = 0.f; acc1[o] = 0.f; }

    int nbeg = ch * 512 + lane;
    #pragma unroll 2
    for (int it = 0; it < 16; it++) {
        int n = nbeg + it * 32;
        float p0 = __expf(k0p[n] - mx0);
        float p1 = __expf(k1p[n] - mx1);
        s0 += p0; s1 += p1;
        #pragma unroll
        for (int o = 0; o < 16; o++) {
            float vv = vbase[(size_t)o * NN + n];
            acc0[o] += p0 * vv;
            acc1[o] += p1 * vv;
        }
    }
    #pragma unroll
    for (int off = 16; off; off >>= 1) {
        s0 += __shfl_xor_sync(0xffffffffu, s0, off);
        s1 += __shfl_xor_sync(0xffffffffu, s1, off);
        #pragma unroll
        for (int o = 0; o < 16; o++) {
            acc0[o] += __shfl_xor_sync(0xffffffffu, acc0[o], off);
            acc1[o] += __shfl_xor_sync(0xffffffffu, acc1[o], off);
        }
    }
    if (lane == 0) {
        float* pn = g_pnum + (size_t)(h * 8 + ch) * 256;
        #pragma unroll
        for (int o = 0; o < 16; o++) {
            pn[i0 * 16 + o]       = acc0[o];
            pn[(i0 + 1) * 16 + o] = acc1[o];
        }
        g_pden[(h * 8 + ch) * 16 + i0]     = s0;
        g_pden[(h * 8 + ch) * 16 + i0 + 1] = s1;
    }
}

// ============================================================================
// K3c: combine partials -> lambda (0.25 scaling folded in)
// ============================================================================
__global__ __launch_bounds__(256) void lambda_comb_kernel()
{
    int h = blockIdx.x, t = threadIdx.x;
    int i = t >> 4;
    float num = 0.f, den = 0.f;
    #pragma unroll
    for (int ch = 0; ch < 8; ch++) {
        num += g_pnum[(size_t)(h * 8 + ch) * 256 + t];
        den += g_pden[(h * 8 + ch) * 16 + i];
    }
    g_lambda[h * 256 + t] = 0.25f * num / den;
}

// ============================================================================
// K4: result1 = content_output + q * dwconv5x5(v, rel_pos)
// ============================================================================
__global__ __launch_bounds__(256) void attn_out_kernel(const float* __restrict__ rel_pos)
{
    __shared__ float vs[16][20][20];
    __shared__ float ls[16][16];
    __shared__ float rw[16][25];

    int h = blockIdx.z;
    int b = h >> 3, nh = h & 7;
    int x0 = blockIdx.x * 16, y0 = blockIdx.y * 16;

    const float* vbase = g_qkv + (size_t)(b * 384 + 256 + nh * 16) * NN;
    const float* qbase = g_qkv + (size_t)(b * 384 +   0 + nh * 16) * NN;

    int tid = threadIdx.x;
    int tx = tid & 15, ty = tid >> 4;

    ls[tid >> 4][tid & 15] = g_lambda[h * 256 + tid];
    for (int i = tid; i < 400; i += 256) rw[i / 25][i % 25] = rel_pos[i];

    for (int i = tid; i < 16 * 400; i += 256) {
        int chn = i / 400, r = i % 400;
        int yy = y0 + r / 20 - 2, xx = x0 + (r % 20) - 2;
        float val = 0.f;
        if ((unsigned)yy < HH && (unsigned)xx < WW)
            val = vbase[(size_t)chn * NN + yy * 64 + xx];
        vs[chn][r / 20][r % 20] = val;
    }
    __syncthreads();

    int y = y0 + ty, x = x0 + tx;
    int n = y * 64 + x;

    float q[16];
    #pragma unroll
    for (int i = 0; i < 16; i++) q[i] = qbase[(size_t)i * NN + n];

    float* r1base = g_r1 + (size_t)(b * 128 + nh * 16) * NN + n;
    #pragma unroll
    for (int o = 0; o < 16; o++) {
        float cont = 0.f;
        #pragma unroll
        for (int i = 0; i < 16; i++) cont += q[i] * ls[i][o];
        float pos = 0.f;
        #pragma unroll
        for (int ky = 0; ky < 5; ky++)
            #pragma unroll
            for (int kx = 0; kx < 5; kx++)
                pos += rw[o][ky * 5 + kx] * vs[o][ty + ky][tx + kx];
        r1base[(size_t)o * NN] = cont + q[o] * pos;
    }
}

// ============================================================================
// K5: ECA channel attention
// ============================================================================
__global__ __launch_bounds__(128) void ca_kernel(const float* __restrict__ conv1d_w)
{
    int b = blockIdx.x, c = threadIdx.x;
    const float* pp = g_pool + b * CC;
    float pm1 = (c > 0)      ? pp[c - 1] : 0.f;
    float p0  = pp[c];
    float pp1 = (c < CC - 1) ? pp[c + 1] : 0.f;
    float z = conv1d_w[0] * pm1 + conv1d_w[1] * p0 + conv1d_w[2] * pp1;
    g_ca[b * CC + c] = 1.f / (1.f + expf(-z));
}

// ============================================================================
// K6: output projection (512 x 256) @ cat(result1, src*ca), split-bf16 mma
// ============================================================================
__global__ __launch_bounds__(256) void out_gemm_kernel(
    const float* __restrict__ out_w, const float* __restrict__ src,
    float* __restrict__ out)
{
    __shared__ uint32_t sWh[8][132], sWl[8][132];
    __shared__ uint32_t sXh[8][132], sXl[8][132];

    int b  = blockIdx.z;
    int n0 = blockIdx.x * 128;
    int m0 = blockIdx.y * 128;

    const float* r1b  = g_r1 + (size_t)b * CC * NN;
    const float* srcb = src  + (size_t)b * CC * NN;
    const float* cab  = g_ca + b * CC;

    int tid  = threadIdx.x;
    int warp = tid >> 5, lane = tid & 31;
    int wm = (warp & 1) * 64;
    int wn = (warp >> 1) * 32;
    int gid = lane >> 2, tig = lane & 3;

    float acc[16][4];
    #pragma unroll
    for (int i = 0; i < 16; i++)
        #pragma unroll
        for (int j = 0; j < 4; j++) acc[i][j] = 0.f;

    for (int k0 = 0; k0 < 256; k0 += 16) {
        #pragma unroll
        for (int r = 0; r < 4; r++) {
            int idx = tid + r * 256;
            int m = idx >> 3, k8 = idx & 7;
            float2 w2 = *(const float2*)&out_w[(m0 + m) * 256 + k0 + k8 * 2];
            bf16_split2(w2.x, w2.y, sWh[k8][m], sWl[k8][m]);
            int n = idx & 127, k8b = idx >> 7;
            int cg = k0 + k8b * 2;          // pair stays within one region
            float x0, x1;
            if (cg < 128) {
                x0 = r1b[(size_t)cg * NN + n0 + n];
                x1 = r1b[(size_t)(cg + 1) * NN + n0 + n];
            } else {
                float s0c = cab[cg - 128], s1c = cab[cg - 127];
                x0 = srcb[(size_t)(cg - 128) * NN + n0 + n] * s0c;
                x1 = srcb[(size_t)(cg - 127) * NN + n0 + n] * s1c;
            }
            bf16_split2(x0, x1, sXh[k8b][n], sXl[k8b][n]);
        }
        __syncthreads();

        uint32_t ah[4][4], al[4][4], bh[4][2], bl[4][2];
        #pragma unroll
        for (int am = 0; am < 4; am++) {
            int mr = wm + am * 16 + gid;
            ah[am][0] = sWh[tig][mr];     al[am][0] = sWl[tig][mr];
            ah[am][1] = sWh[tig][mr + 8]; al[am][1] = sWl[tig][mr + 8];
            ah[am][2] = sWh[tig + 4][mr];     al[am][2] = sWl[tig + 4][mr];
            ah[am][3] = sWh[tig + 4][mr + 8]; al[am][3] = sWl[tig + 4][mr + 8];
        }
        #pragma unroll
        for (int an = 0; an < 4; an++) {
            int nc = wn + an * 8 + gid;
            bh[an][0] = sXh[tig][nc];     bl[an][0] = sXl[tig][nc];
            bh[an][1] = sXh[tig + 4][nc]; bl[an][1] = sXl[tig + 4][nc];
        }
        #pragma unroll
        for (int am = 0; am < 4; am++)
            #pragma unroll
            for (int an = 0; an < 4; an++) {
                float* d = acc[am * 4 + an];
                mma_bf16(d, ah[am], bh[an]);
                mma_bf16(d, al[am], bh[an]);
                mma_bf16(d, ah[am], bl[an]);
            }
        __syncthreads();
    }

    #pragma unroll
    for (int am = 0; am < 4; am++)
        #pragma unroll
        for (int an = 0; an < 4; an++) {
            const float* d = acc[am * 4 + an];
            int row = m0 + wm + am * 16 + gid;
            int col = n0 + wn + an * 8 + 2 * tig;
            float* dst = out + (size_t)(b * OUTC + row) * NN + col;
            *(float2*)dst            = make_float2(d[0], d[1]);
            *(float2*)(dst + 8 * NN) = make_float2(d[2], d[3]);
        }
}

// ============================================================================
extern "C" void kernel_launch(void* const* d_in, const int* in_sizes, int n_in,
                              void* d_out, int out_size)
{
    const float* src      = (const float*)d_in[0];  // (16,128,64,64)
    const float* cpe_w    = (const float*)d_in[1];  // (128,1,3,3)
    const float* qkv_w    = (const float*)d_in[2];  // (384,128)
    const float* rel_pos  = (const float*)d_in[3];  // (16,5,5)
    const float* conv1d_w = (const float*)d_in[4];  // (3,)
    const float* out_w    = (const float*)d_in[5];  // (512,256)
    float* out = (float*)d_out;                     // (16,512,64,64)

    cpe_pool_kernel<<<BB * CC, 256>>>(src, cpe_w);
    ca_kernel<<<BB, 128>>>(conv1d_w);
    qkv_gemm_kernel<<<dim3(NN / 128, 3, BB), 256>>>(qkv_w);
    kmax_kernel<<<NHEADS * HDD / 8, 256>>>();
    lambda_part_kernel<<<dim3(8, NHEADS), 256>>>();
    lambda_comb_kernel<<<NHEADS, 256>>>();
    attn_out_kernel<<<dim3(4, 4, NHEADS), 256>>>(rel_pos);
    out_gemm_kernel<<<dim3(NN / 128, OUTC / 128, BB), 256>>>(out_w, src, out);
}

// round 10
// speedup vs baseline: 3.0128x; 1.3121x over previous
#include <cuda_runtime.h>
#include <cuda_bf16.h>
#include <math.h>
#include <stdint.h>

#define BB 16
#define CC 128
#define HH 64
#define WW 64
#define NN 4096      // HH*WW
#define NHH 8
#define HDD 16
#define NHEADS 128   // BB*NHH
#define OUTC 512

// ---------------- scratch (static device globals; no allocation allowed) ----
__device__ float    g_qkv[BB * 3 * CC * NN];   // 100.7 MB : q|k|v (b, 384, n)
__device__ float    g_lambda[NHEADS * HDD * HDD];
__device__ float    g_pool[BB * CC];
__device__ float    g_ca[BB * CC];
__device__ float    g_pnum[NHEADS * 8 * 256];
__device__ float    g_pden[NHEADS * 8 * 16];
// packed bf16x2 operand planes (hi/lo split), pairs along K(channel)
__device__ uint32_t g_sh[BB * 64 * NN];        // 16.8 MB : CPE output (pairs)
__device__ uint32_t g_sl[BB * 64 * NN];
__device__ uint32_t g_xh[BB * 128 * NN];       // 33.5 MB : cat(r1, src*ca) pairs
__device__ uint32_t g_xl[BB * 128 * NN];
__device__ uint32_t g_wqh[64 * 384],  g_wql[64 * 384];   // qkv_w packed [k8][m]
__device__ uint32_t g_woh[128 * 512], g_wol[128 * 512];  // out_w packed [k8][m]

// ---------------------------------------------------------------------------
__device__ __forceinline__ void bf16_split2(float x0, float x1,
                                            uint32_t& hi, uint32_t& lo)
{
    __nv_bfloat16 h0 = __float2bfloat16_rn(x0);
    __nv_bfloat16 h1 = __float2bfloat16_rn(x1);
    __nv_bfloat16 l0 = __float2bfloat16_rn(x0 - __bfloat162float(h0));
    __nv_bfloat16 l1 = __float2bfloat16_rn(x1 - __bfloat162float(h1));
    hi = ((uint32_t)__bfloat16_as_ushort(h1) << 16) | __bfloat16_as_ushort(h0);
    lo = ((uint32_t)__bfloat16_as_ushort(l1) << 16) | __bfloat16_as_ushort(l0);
}

__device__ __forceinline__ void mma_bf16(float* d, const uint32_t* a, const uint32_t* b)
{
    asm volatile(
        "mma.sync.aligned.m16n8k16.row.col.f32.bf16.bf16.f32 "
        "{%0,%1,%2,%3}, {%4,%5,%6,%7}, {%8,%9}, {%0,%1,%2,%3};"
        : "+f"(d[0]), "+f"(d[1]), "+f"(d[2]), "+f"(d[3])
        : "r"(a[0]), "r"(a[1]), "r"(a[2]), "r"(a[3]), "r"(b[0]), "r"(b[1]));
}

__device__ __forceinline__ uint32_t smem_u32(const void* p) {
    uint32_t a;
    asm("{ .reg .u64 t; cvta.to.shared.u64 t, %1; cvt.u32.u64 %0, t; }"
        : "=r"(a) : "l"(p));
    return a;
}
#define CPA16(dst, src) \
    asm volatile("cp.async.cg.shared.global [%0], [%1], 16;" :: "r"(dst), "l"(src) : "memory")
#define CPA_COMMIT() asm volatile("cp.async.commit_group;" ::: "memory")

// ============================================================================
// K1: CPE dw3x3 + residual for a channel PAIR, fused pooling, packed output
// grid (64 cpair, 16 b), 256 thr
// ============================================================================
__global__ __launch_bounds__(256) void cpe_pool_kernel(
    const float* __restrict__ src, const float* __restrict__ cpe_w)
{
    __shared__ float tile[2][HH][WW];   // 32 KB
    __shared__ float2 red[256];

    int cp = blockIdx.x, b = blockIdx.y;
    int c0 = cp * 2;
    int tid = threadIdx.x;
    const float* p0 = src + ((size_t)b * CC + c0) * NN;
    const float* p1 = p0 + NN;

    float s0 = 0.f, s1 = 0.f;
    #pragma unroll 4
    for (int i = tid; i < NN; i += 256) {
        float v0 = p0[i], v1 = p1[i];
        tile[0][i >> 6][i & 63] = v0;
        tile[1][i >> 6][i & 63] = v1;
        s0 += v0; s1 += v1;
    }
    red[tid] = make_float2(s0, s1);
    __syncthreads();
    for (int s = 128; s > 0; s >>= 1) {
        if (tid < s) {
            red[tid].x += red[tid + s].x;
            red[tid].y += red[tid + s].y;
        }
        __syncthreads();
    }
    if (tid == 0) {
        g_pool[b * CC + c0]     = red[0].x * (1.f / (float)NN);
        g_pool[b * CC + c0 + 1] = red[0].y * (1.f / (float)NN);
    }

    float w0[9], w1[9];
    #pragma unroll
    for (int j = 0; j < 9; j++) { w0[j] = cpe_w[c0 * 9 + j]; w1[j] = cpe_w[c0 * 9 + 9 + j]; }

    uint32_t* dh = g_sh + ((size_t)b * 64 + cp) * NN;
    uint32_t* dl = g_sl + ((size_t)b * 64 + cp) * NN;
    for (int i = tid; i < NN; i += 256) {
        int y = i >> 6, x = i & 63;
        float a0 = tile[0][y][x], a1 = tile[1][y][x];
        #pragma unroll
        for (int ky = 0; ky < 3; ky++) {
            int yy = y + ky - 1;
            if ((unsigned)yy >= HH) continue;
            #pragma unroll
            for (int kx = 0; kx < 3; kx++) {
                int xx = x + kx - 1;
                if ((unsigned)xx >= WW) continue;
                a0 += w0[ky * 3 + kx] * tile[0][yy][xx];
                a1 += w1[ky * 3 + kx] * tile[1][yy][xx];
            }
        }
        uint32_t hi, lo;
        bf16_split2(a0, a1, hi, lo);
        dh[i] = hi; dl[i] = lo;
    }
}

// ============================================================================
// K2: pack weights -> [k8][m] hi/lo planes
// ============================================================================
__global__ __launch_bounds__(256) void pack_w_kernel(
    const float* __restrict__ qkv_w, const float* __restrict__ out_w)
{
    int idx = blockIdx.x * 256 + threadIdx.x;
    if (idx < 64 * 384) {
        int k8 = idx / 384, m = idx % 384;
        float2 w2 = *(const float2*)&qkv_w[m * 128 + k8 * 2];
        bf16_split2(w2.x, w2.y, g_wqh[idx], g_wql[idx]);
    }
    int idx2 = idx - 64 * 384;
    if (idx2 >= 0 && idx2 < 128 * 512) {
        int k8 = idx2 / 512, m = idx2 % 512;
        float2 w2 = *(const float2*)&out_w[m * 256 + k8 * 2];
        bf16_split2(w2.x, w2.y, g_woh[idx2], g_wol[idx2]);
    }
}

// ============================================================================
// K3: ECA channel attention weights
// ============================================================================
__global__ __launch_bounds__(128) void ca_kernel(const float* __restrict__ conv1d_w)
{
    int b = blockIdx.x, c = threadIdx.x;
    const float* pp = g_pool + b * CC;
    float pm1 = (c > 0)      ? pp[c - 1] : 0.f;
    float p0  = pp[c];
    float pp1 = (c < CC - 1) ? pp[c + 1] : 0.f;
    float z = conv1d_w[0] * pm1 + conv1d_w[1] * p0 + conv1d_w[2] * pp1;
    g_ca[b * CC + c] = 1.f / (1.f + expf(-z));
}

// ============================================================================
// K4: pack src*ca into g_x rows 64..127  -- grid (64 cp, 16 b)
// ============================================================================
__global__ __launch_bounds__(256) void pack_src_kernel(const float* __restrict__ src)
{
    int cp = blockIdx.x, b = blockIdx.y;
    int tid = threadIdx.x;
    const float* p0 = src + ((size_t)b * CC + cp * 2) * NN;
    const float* p1 = p0 + NN;
    float ca0 = g_ca[b * CC + cp * 2];
    float ca1 = g_ca[b * CC + cp * 2 + 1];
    uint32_t* dh = g_xh + ((size_t)b * 128 + 64 + cp) * NN;
    uint32_t* dl = g_xl + ((size_t)b * 128 + 64 + cp) * NN;

    #pragma unroll
    for (int it = 0; it < 4; it++) {
        int i = (it * 256 + tid) * 4;
        float4 a = *(const float4*)&p0[i];
        float4 c4 = *(const float4*)&p1[i];
        uint4 h, l;
        bf16_split2(a.x * ca0, c4.x * ca1, h.x, l.x);
        bf16_split2(a.y * ca0, c4.y * ca1, h.y, l.y);
        bf16_split2(a.z * ca0, c4.z * ca1, h.z, l.z);
        bf16_split2(a.w * ca0, c4.w * ca1, h.w, l.w);
        *(uint4*)&dh[i] = h;
        *(uint4*)&dl[i] = l;
    }
}

// ============================================================================
// K5: unified split-bf16 GEMM, cp.async double-buffered
// MODE 0: qkv  (M=384, K8=64,  B=g_s*,  C=g_qkv)
// MODE 1: out  (M=512, K8=128, B=g_x*,  C=Cout)
// ============================================================================
template<int MODE>
__global__ __launch_bounds__(256) void gemm_kernel(float* __restrict__ Cout)
{
    constexpr int M  = MODE ? 512 : 384;
    constexpr int K8 = MODE ? 128 : 64;
    constexpr int NC = K8 / 8;

    __shared__ uint32_t sAh[2][8][132], sAl[2][8][132];
    __shared__ uint32_t sBh[2][8][132], sBl[2][8][132];

    const uint32_t* Ah = MODE ? g_woh : g_wqh;
    const uint32_t* Al = MODE ? g_wol : g_wql;

    int b  = blockIdx.z;
    int n0 = blockIdx.x * 128;
    int m0 = blockIdx.y * 128;

    const uint32_t* Bh = (MODE ? g_xh : g_sh) + (size_t)b * K8 * NN;
    const uint32_t* Bl = (MODE ? g_xl : g_sl) + (size_t)b * K8 * NN;
    float* C = MODE ? (Cout + (size_t)b * OUTC * NN)
                    : (g_qkv + (size_t)b * 3 * CC * NN);

    int tid  = threadIdx.x;
    int warp = tid >> 5, lane = tid & 31;
    int wm = (warp & 1) * 64;
    int wn = (warp >> 1) * 32;
    int gid = lane >> 2, tig = lane & 3;
    int arow = tid >> 5, aseg = tid & 31;   // stage mapping: 8 rows x 32 segs

    float acc[16][4];
    #pragma unroll
    for (int i = 0; i < 16; i++)
        #pragma unroll
        for (int j = 0; j < 4; j++) acc[i][j] = 0.f;

    // ---- stage chunk 0
    {
        int k8 = arow;
        CPA16(smem_u32(&sAh[0][arow][aseg * 4]), Ah + (size_t)k8 * M + m0 + aseg * 4);
        CPA16(smem_u32(&sAl[0][arow][aseg * 4]), Al + (size_t)k8 * M + m0 + aseg * 4);
        CPA16(smem_u32(&sBh[0][arow][aseg * 4]), Bh + (size_t)k8 * NN + n0 + aseg * 4);
        CPA16(smem_u32(&sBl[0][arow][aseg * 4]), Bl + (size_t)k8 * NN + n0 + aseg * 4);
        CPA_COMMIT();
    }

    #pragma unroll 1
    for (int c = 0; c < NC; c++) {
        if (c + 1 < NC) {
            int buf = (c + 1) & 1, k8 = (c + 1) * 8 + arow;
            CPA16(smem_u32(&sAh[buf][arow][aseg * 4]), Ah + (size_t)k8 * M + m0 + aseg * 4);
            CPA16(smem_u32(&sAl[buf][arow][aseg * 4]), Al + (size_t)k8 * M + m0 + aseg * 4);
            CPA16(smem_u32(&sBh[buf][arow][aseg * 4]), Bh + (size_t)k8 * NN + n0 + aseg * 4);
            CPA16(smem_u32(&sBl[buf][arow][aseg * 4]), Bl + (size_t)k8 * NN + n0 + aseg * 4);
            CPA_COMMIT();
            asm volatile("cp.async.wait_group 1;" ::: "memory");
        } else {
            asm volatile("cp.async.wait_group 0;" ::: "memory");
        }
        __syncthreads();

        int bf = c & 1;
        uint32_t ah[4][4], al[4][4], bh[4][2], bl[4][2];
        #pragma unroll
        for (int am = 0; am < 4; am++) {
            int mr = wm + am * 16 + gid;
            ah[am][0] = sAh[bf][tig][mr];     al[am][0] = sAl[bf][tig][mr];
            ah[am][1] = sAh[bf][tig][mr + 8]; al[am][1] = sAl[bf][tig][mr + 8];
            ah[am][2] = sAh[bf][tig + 4][mr];     al[am][2] = sAl[bf][tig + 4][mr];
            ah[am][3] = sAh[bf][tig + 4][mr + 8]; al[am][3] = sAl[bf][tig + 4][mr + 8];
        }
        #pragma unroll
        for (int an = 0; an < 4; an++) {
            int nc = wn + an * 8 + gid;
            bh[an][0] = sBh[bf][tig][nc];     bl[an][0] = sBl[bf][tig][nc];
            bh[an][1] = sBh[bf][tig + 4][nc]; bl[an][1] = sBl[bf][tig + 4][nc];
        }
        #pragma unroll
        for (int am = 0; am < 4; am++)
            #pragma unroll
            for (int an = 0; an < 4; an++) {
                float* d = acc[am * 4 + an];
                mma_bf16(d, ah[am], bh[an]);
                mma_bf16(d, al[am], bh[an]);
                mma_bf16(d, ah[am], bl[an]);
            }
        __syncthreads();
    }

    #pragma unroll
    for (int am = 0; am < 4; am++)
        #pragma unroll
        for (int an = 0; an < 4; an++) {
            const float* d = acc[am * 4 + an];
            int row = m0 + wm + am * 16 + gid;
            int col = n0 + wn + an * 8 + 2 * tig;
            float* dst = C + (size_t)row * NN + col;
            *(float2*)dst            = make_float2(d[0], d[1]);
            *(float2*)(dst + 8 * NN) = make_float2(d[2], d[3]);
        }
}

// ============================================================================
// K6: partial lambda over N-chunks (no max subtraction; k is O(10) bounded)
// ============================================================================
__global__ __launch_bounds__(256) void lambda_part_kernel()
{
    int ch = blockIdx.x, h = blockIdx.y;
    int b = h >> 3, nh = h & 7;
    int warp = threadIdx.x >> 5, lane = threadIdx.x & 31;
    int i0 = warp * 2;

    const float* kbase = g_qkv + (size_t)(b * 384 + 128 + nh * 16) * NN;
    const float* vbase = g_qkv + (size_t)(b * 384 + 256 + nh * 16) * NN;
    const float* k0p = kbase + (size_t)i0 * NN;
    const float* k1p = k0p + NN;

    float acc0[16], acc1[16], s0 = 0.f, s1 = 0.f;
    #pragma unroll
    for (int o = 0; o < 16; o++) { acc0[o] = 0.f; acc1[o] = 0.f; }

    int nbeg = ch * 512 + lane;
    #pragma unroll 2
    for (int it = 0; it < 16; it++) {
        int n = nbeg + it * 32;
        float p0 = __expf(k0p[n]);
        float p1 = __expf(k1p[n]);
        s0 += p0; s1 += p1;
        #pragma unroll
        for (int o = 0; o < 16; o++) {
            float vv = vbase[(size_t)o * NN + n];
            acc0[o] += p0 * vv;
            acc1[o] += p1 * vv;
        }
    }
    #pragma unroll
    for (int off = 16; off; off >>= 1) {
        s0 += __shfl_xor_sync(0xffffffffu, s0, off);
        s1 += __shfl_xor_sync(0xffffffffu, s1, off);
        #pragma unroll
        for (int o = 0; o < 16; o++) {
            acc0[o] += __shfl_xor_sync(0xffffffffu, acc0[o], off);
            acc1[o] += __shfl_xor_sync(0xffffffffu, acc1[o], off);
        }
    }
    if (lane == 0) {
        float* pn = g_pnum + (size_t)(h * 8 + ch) * 256;
        #pragma unroll
        for (int o = 0; o < 16; o++) {
            pn[i0 * 16 + o]       = acc0[o];
            pn[(i0 + 1) * 16 + o] = acc1[o];
        }
        g_pden[(h * 8 + ch) * 16 + i0]     = s0;
        g_pden[(h * 8 + ch) * 16 + i0 + 1] = s1;
    }
}

// ============================================================================
// K7: combine partials -> lambda
// ============================================================================
__global__ __launch_bounds__(256) void lambda_comb_kernel()
{
    int h = blockIdx.x, t = threadIdx.x;
    int i = t >> 4;
    float num = 0.f, den = 0.f;
    #pragma unroll
    for (int ch = 0; ch < 8; ch++) {
        num += g_pnum[(size_t)(h * 8 + ch) * 256 + t];
        den += g_pden[(h * 8 + ch) * 16 + i];
    }
    g_lambda[h * 256 + t] = 0.25f * num / den;
}

// ============================================================================
// K8: result1 = content + q * dwconv5x5(v), packed bf16 pair output
// ============================================================================
__global__ __launch_bounds__(256) void attn_out_kernel(const float* __restrict__ rel_pos)
{
    __shared__ float vs[16][20][20];
    __shared__ float ls[16][16];
    __shared__ float rw[16][25];

    int h = blockIdx.z;
    int b = h >> 3, nh = h & 7;
    int x0 = blockIdx.x * 16, y0 = blockIdx.y * 16;

    const float* vbase = g_qkv + (size_t)(b * 384 + 256 + nh * 16) * NN;
    const float* qbase = g_qkv + (size_t)(b * 384 +   0 + nh * 16) * NN;

    int tid = threadIdx.x;
    int tx = tid & 15, ty = tid >> 4;

    ls[tid >> 4][tid & 15] = g_lambda[h * 256 + tid];
    for (int i = tid; i < 400; i += 256) rw[i / 25][i % 25] = rel_pos[i];

    for (int i = tid; i < 16 * 400; i += 256) {
        int chn = i / 400, r = i % 400;
        int yy = y0 + r / 20 - 2, xx = x0 + (r % 20) - 2;
        float val = 0.f;
        if ((unsigned)yy < HH && (unsigned)xx < WW)
            val = vbase[(size_t)chn * NN + yy * 64 + xx];
        vs[chn][r / 20][r % 20] = val;
    }
    __syncthreads();

    int y = y0 + ty, x = x0 + tx;
    int n = y * 64 + x;

    float q[16];
    #pragma unroll
    for (int i = 0; i < 16; i++) q[i] = qbase[(size_t)i * NN + n];

    float res[16];
    #pragma unroll
    for (int o = 0; o < 16; o++) {
        float cont = 0.f;
        #pragma unroll
        for (int i = 0; i < 16; i++) cont += q[i] * ls[i][o];
        float pos = 0.f;
        #pragma unroll
        for (int ky = 0; ky < 5; ky++)
            #pragma unroll
            for (int kx = 0; kx < 5; kx++)
                pos += rw[o][ky * 5 + kx] * vs[o][ty + ky][tx + kx];
        res[o] = cont + q[o] * pos;
    }

    uint32_t* xh = g_xh + ((size_t)b * 128 + nh * 8) * NN + n;
    uint32_t* xl = g_xl + ((size_t)b * 128 + nh * 8) * NN + n;
    #pragma unroll
    for (int o2 = 0; o2 < 8; o2++) {
        uint32_t hi, lo;
        bf16_split2(res[2 * o2], res[2 * o2 + 1], hi, lo);
        xh[(size_t)o2 * NN] = hi;
        xl[(size_t)o2 * NN] = lo;
    }
}

// ============================================================================
extern "C" void kernel_launch(void* const* d_in, const int* in_sizes, int n_in,
                              void* d_out, int out_size)
{
    const float* src      = (const float*)d_in[0];  // (16,128,64,64)
    const float* cpe_w    = (const float*)d_in[1];  // (128,1,3,3)
    const float* qkv_w    = (const float*)d_in[2];  // (384,128)
    const float* rel_pos  = (const float*)d_in[3];  // (16,5,5)
    const float* conv1d_w = (const float*)d_in[4];  // (3,)
    const float* out_w    = (const float*)d_in[5];  // (512,256)
    float* out = (float*)d_out;                     // (16,512,64,64)

    pack_w_kernel<<<(64 * 384 + 128 * 512 + 255) / 256, 256>>>(qkv_w, out_w);
    cpe_pool_kernel<<<dim3(64, BB), 256>>>(src, cpe_w);
    ca_kernel<<<BB, 128>>>(conv1d_w);
    pack_src_kernel<<<dim3(64, BB), 256>>>(src);
    gemm_kernel<0><<<dim3(32, 3, BB), 256>>>(nullptr);
    lambda_part_kernel<<<dim3(8, NHEADS), 256>>>();
    lambda_comb_kernel<<<NHEADS, 256>>>();
    attn_out_kernel<<<dim3(4, 4, NHEADS), 256>>>(rel_pos);
    gemm_kernel<1><<<dim3(32, 4, BB), 256>>>(out);
}